// round 3
// baseline (speedup 1.0000x reference)
#include <cuda_runtime.h>

#define HW (768*768)
#define NB 32

// XLA algebraic-simplifier semantics: x / const -> x * (1/const), with the
// reciprocal rounded once at compile time.
__device__ __constant__ const float C3  = 1.0f / 3.0f;   // 0x3EAAAAAB
__device__ __constant__ const float C81 = 1.0f / 81.0f;

// scratch: interleaved (sx, sy) per pixel
__device__ __align__(16) float2 g_s[(size_t)NB * HW];

// ---------------------------------------------------------------------------
// Kernel 1: M = channel mean (zero-padded) via sum * (1/3), Sobel-equivalent
// with the exact reference op order:
//   rlx = m(i,j+1)-m(i,j-1);  sx = rlx + ((rlx_u + rlx_c + rlx_d)*(1/3))*3
//   btx = m(i+1,j)-m(i-1,j);  sy = btx + ((btx_l + btx_c + btx_r)*(1/3))*3
// All ops in explicit round-to-nearest intrinsics (no fma contraction).
// ---------------------------------------------------------------------------
__global__ void __launch_bounds__(256) k_sobel(const float* __restrict__ x) {
    __shared__ float M[34 * 72];   // rows row0-1..row0+32, cols col0-4..col0+67

    const int col0 = blockIdx.x * 64;
    const int row0 = blockIdx.y * 32;
    const int b    = blockIdx.z;
    const int t    = threadIdx.x;
    const float* xb = x + (size_t)b * 3 * HW;

    for (int s = t; s < 34 * 18; s += 256) {
        int rr = s / 18, k = s - rr * 18;
        int gr = row0 - 1 + rr;
        int gc = col0 - 4 + 4 * k;
        float4 v = make_float4(0.f, 0.f, 0.f, 0.f);
        if ((unsigned)gr < 768u && (unsigned)gc <= 764u) {
            size_t off = (size_t)gr * 768 + gc;
            float4 a  = *(const float4*)(xb + off);
            float4 c1 = *(const float4*)(xb + HW + off);
            float4 c2 = *(const float4*)(xb + 2 * HW + off);
            v.x = __fmul_rn(__fadd_rn(__fadd_rn(a.x, c1.x), c2.x), C3);
            v.y = __fmul_rn(__fadd_rn(__fadd_rn(a.y, c1.y), c2.y), C3);
            v.z = __fmul_rn(__fadd_rn(__fadd_rn(a.z, c1.z), c2.z), C3);
            v.w = __fmul_rn(__fadd_rn(__fadd_rn(a.w, c1.w), c2.w), C3);
        }
        *(float4*)&M[rr * 72 + 4 * k] = v;
    }
    __syncthreads();

    const int c  = t & 63;
    const int rg = t >> 6;        // 0..3, each handles 8 rows
    const int sc = c + 4;
    float2* sb = g_s + (size_t)b * HW;

    #pragma unroll
    for (int i = 0; i < 8; i++) {
        int rl = rg * 8 + i;
        int sr = rl + 1;
        const float* r0p = &M[(sr - 1) * 72 + sc];
        const float* r1p = &M[ sr      * 72 + sc];
        const float* r2p = &M[(sr + 1) * 72 + sc];
        float m00 = r0p[-1], m01 = r0p[0], m02 = r0p[1];
        float m10 = r1p[-1],               m12 = r1p[1];
        float m20 = r2p[-1], m21 = r2p[0], m22 = r2p[1];

        float rlx_u = __fsub_rn(m02, m00);
        float rlx_c = __fsub_rn(m12, m10);
        float rlx_d = __fsub_rn(m22, m20);
        float tx3 = __fadd_rn(__fadd_rn(rlx_u, rlx_c), rlx_d);
        float sxv = __fadd_rn(rlx_c, __fmul_rn(__fmul_rn(tx3, C3), 3.f));

        float btx_l = __fsub_rn(m20, m00);
        float btx_c = __fsub_rn(m21, m01);
        float btx_r = __fsub_rn(m22, m02);
        float ty3 = __fadd_rn(__fadd_rn(btx_l, btx_c), btx_r);
        float syv = __fadd_rn(btx_c, __fmul_rn(__fmul_rn(ty3, C3), 3.f));

        sb[(size_t)(row0 + rl) * 768 + col0 + c] = make_float2(sxv, syv);
    }
}

// ---------------------------------------------------------------------------
// Kernel 2: 9x9 box sums of sx^2, sy^2, sx*sy computed with the exact
// reduce_window accumulation order (flat row-major 81-add loop, zero pad),
// scaled by *(1/81), then the eigen chain in strict rn ops.
// Tile 64x32 per 256-thread block.
// ---------------------------------------------------------------------------
__global__ void __launch_bounds__(256) k_struct(float* __restrict__ out) {
    // product arrays: [map][row 0..39][col 0..71], stride 72 (16B-aligned rows)
    __shared__ float P[3][40 * 72];

    const int col0 = blockIdx.x * 64;
    const int row0 = blockIdx.y * 32;
    const int b    = blockIdx.z;
    const int t    = threadIdx.x;
    const float2* sb = g_s + (size_t)b * HW;

    // load halo (rows row0-4..row0+35, cols col0-4..col0+67) as float4
    // (= 2 float2), compute products, store to smem
    for (int s = t; s < 40 * 36; s += 256) {
        int rr = s / 36, k = s - rr * 36;
        int gr = row0 - 4 + rr;
        int g  = col0 - 4 + 2 * k;
        float4 v = make_float4(0.f, 0.f, 0.f, 0.f);
        if ((unsigned)gr < 768u && (unsigned)g <= 766u) {
            v = *(const float4*)&sb[(size_t)gr * 768 + g];
        }
        int cc = rr * 72 + 2 * k;
        *(float2*)&P[0][cc] = make_float2(__fmul_rn(v.x, v.x), __fmul_rn(v.z, v.z));
        *(float2*)&P[1][cc] = make_float2(__fmul_rn(v.y, v.y), __fmul_rn(v.w, v.w));
        *(float2*)&P[2][cc] = make_float2(__fmul_rn(v.x, v.y), __fmul_rn(v.z, v.w));
    }
    __syncthreads();

    float* ob = out + (size_t)b * 3 * HW;

    // 512 units of 4 consecutive outputs; 2 units per thread
    #pragma unroll
    for (int uu = 0; uu < 2; uu++) {
        int u  = t + uu * 256;
        int i  = u >> 4;            // output local row 0..31
        int j0 = (u & 15) * 4;      // output local col group

        float acc[3][4];
        #pragma unroll
        for (int m = 0; m < 3; m++) {
            float a0 = 0.f, a1 = 0.f, a2 = 0.f, a3 = 0.f;
            #pragma unroll
            for (int r = 0; r < 9; r++) {
                const float* row = &P[m][(i + r) * 72 + j0];
                float4 A = *(const float4*)(row);
                float4 B = *(const float4*)(row + 4);
                float4 C = *(const float4*)(row + 8);
                float w0 = A.x, w1 = A.y, w2 = A.z, w3 = A.w;
                float w4 = B.x, w5 = B.y, w6 = B.z, w7 = B.w;
                float w8 = C.x, w9 = C.y, w10 = C.z, w11 = C.w;
                // flat row-major accumulation, 9 sequential adds per output
                a0 = __fadd_rn(a0, w0); a0 = __fadd_rn(a0, w1); a0 = __fadd_rn(a0, w2);
                a0 = __fadd_rn(a0, w3); a0 = __fadd_rn(a0, w4); a0 = __fadd_rn(a0, w5);
                a0 = __fadd_rn(a0, w6); a0 = __fadd_rn(a0, w7); a0 = __fadd_rn(a0, w8);

                a1 = __fadd_rn(a1, w1); a1 = __fadd_rn(a1, w2); a1 = __fadd_rn(a1, w3);
                a1 = __fadd_rn(a1, w4); a1 = __fadd_rn(a1, w5); a1 = __fadd_rn(a1, w6);
                a1 = __fadd_rn(a1, w7); a1 = __fadd_rn(a1, w8); a1 = __fadd_rn(a1, w9);

                a2 = __fadd_rn(a2, w2); a2 = __fadd_rn(a2, w3); a2 = __fadd_rn(a2, w4);
                a2 = __fadd_rn(a2, w5); a2 = __fadd_rn(a2, w6); a2 = __fadd_rn(a2, w7);
                a2 = __fadd_rn(a2, w8); a2 = __fadd_rn(a2, w9); a2 = __fadd_rn(a2, w10);

                a3 = __fadd_rn(a3, w3); a3 = __fadd_rn(a3, w4); a3 = __fadd_rn(a3, w5);
                a3 = __fadd_rn(a3, w6); a3 = __fadd_rn(a3, w7); a3 = __fadd_rn(a3, w8);
                a3 = __fadd_rn(a3, w9); a3 = __fadd_rn(a3, w10); a3 = __fadd_rn(a3, w11);
            }
            acc[m][0] = a0; acc[m][1] = a1; acc[m][2] = a2; acc[m][3] = a3;
        }

        float ex[4], ey[4];
        #pragma unroll
        for (int k = 0; k < 4; k++) {
            float xx = __fmul_rn(acc[0][k], C81);
            float yy = __fmul_rn(acc[1][k], C81);
            float xy = __fmul_rn(acc[2][k], C81);
            float bq = -__fadd_rn(xx, yy);
            float cq = __fsub_rn(__fmul_rn(xx, yy), __fmul_rn(xy, xy));
            float disc = __fsub_rn(__fmul_rn(bq, bq), __fmul_rn(4.f, cq));
            disc = fmaxf(disc, 0.f);
            float deta = __fsqrt_rn(disc);
            float l1 = __fmul_rn(__fadd_rn(-bq, deta), 0.5f);
            float xd = xy;
            float yd = __fsub_rn(xx, l1);
            float s2 = __fadd_rn(__fadd_rn(__fmul_rn(xd, xd), __fmul_rn(yd, yd)), 1e-8f);
            float l  = __fadd_rn(__fsqrt_rn(s2), 1e-8f);
            ex[k] = __fdiv_rn(xd, l);
            ey[k] = __fdiv_rn(yd, l);
        }

        size_t o = (size_t)(row0 + i) * 768 + (col0 + j0);
        *(float4*)&ob[o]          = make_float4(ex[0], ex[1], ex[2], ex[3]);
        *(float4*)&ob[o + HW]     = make_float4(ey[0], ey[1], ey[2], ey[3]);
        *(float4*)&ob[o + 2*HW]   = make_float4(ex[0], ex[1], ex[2], ex[3]);
    }
}

extern "C" void kernel_launch(void* const* d_in, const int* in_sizes, int n_in,
                              void* d_out, int out_size) {
    const float* x = (const float*)d_in[0];
    float* out = (float*)d_out;

    dim3 grid(768 / 64, 768 / 32, NB);   // (12, 24, 32)
    k_sobel<<<grid, 256>>>(x);
    k_struct<<<grid, 256>>>(out);
}